// round 13
// baseline (speedup 1.0000x reference)
#include <cuda_runtime.h>
#include <math.h>

#define JW 6
#define ALPHA_C 14.04f            // 2.34 * J
#define GSZ 1024                  // G1 == G2 == 2*H
#define NANG 720
#define NDET 768
#define KPTS (NANG * NDET)
#define NDHALF 385                // detectors gathered: d = 0..384 (Hermitian in detector dim)
#define TWO_PI 6.283185307179586f
#define WTN 1024                  // weight-LUT bins

__device__ float2 g_grid[GSZ * GSZ];          // row-FFT'd padded image (only cols 0..512 written/read)
__device__ float2 g_specT[513 * GSZ];         // HALF spectrum: rows j=0..512

// ---------------------------------------------------------------------------
// I0 (A&S) — normalizer; cancels against apodization's I0(alpha).
// ---------------------------------------------------------------------------
__device__ __forceinline__ float i0f_dev(float z) {
    if (z < 3.75f) {
        float t = z * (1.0f / 3.75f);
        float t2 = t * t;
        return 1.0f + t2 * (3.5156229f + t2 * (3.0899424f + t2 * (1.2067492f
                     + t2 * (0.2659732f + t2 * (0.0360768f + t2 * 0.0045813f)))));
    } else {
        float ti = 3.75f / z;
        float p = 0.39894228f + ti * (0.01328592f + ti * (0.00225319f
                + ti * (-0.00157565f + ti * (0.00916281f + ti * (-0.02057706f
                + ti * (0.02635537f + ti * (-0.01647633f + ti * 0.00392377f)))))));
        return p * __expf(z) * rsqrtf(z);
    }
}

// I0(alpha*sqrt(x)) on [0,1]: pure-FMA power series in x (k=16).
__device__ __forceinline__ float i0_alpha_sqrt(float x) {
    float s;
    s = 2.764070f;
    s = fmaf(s, x, 14.35870f);
    s = fmaf(s, x, 65.55800f);
    s = fmaf(s, x, 260.7380f);
    s = fmaf(s, x, 894.1610f);
    s = fmaf(s, x, 2612.787f);
    s = fmaf(s, x, 6415.273f);
    s = fmaf(s, x, 13017.90f);
    s = fmaf(s, x, 21396.99f);
    s = fmaf(s, x, 27788.08f);
    s = fmaf(s, x, 27629.97f);
    s = fmaf(s, x, 20184.07f);
    s = fmaf(s, x, 10239.40f);
    s = fmaf(s, x, 3324.453f);
    s = fmaf(s, x, 607.1395f);
    s = fmaf(s, x, 49.28040f);
    s = fmaf(s, x, 1.0f);
    return s;
}

__device__ __forceinline__ float apod_val(int n, float i0a) {
    float u = (float)(n - 256) * (1.0f / (float)GSZ);
    float t = 3.14159265358979f * (float)JW * u;
    float arg = ALPHA_C * ALPHA_C - t * t;
    float s = sqrtf(fabsf(arg) + 1e-20f);
    float sh;
    if (arg > 0.0f) {
        float e = __expf(s);
        sh = 0.5f * (e - 1.0f / e);
    } else {
        sh = __sinf(s);
    }
    float F = (sh / s) * ((float)JW / i0a);
    return 1.0f / F;
}

// Base-4 digit reversal of a 10-bit index (1024 = 4^5).
__device__ __forceinline__ int rev4_10(int t) {
    int x = __brev(t) >> 22;
    return ((x & 0x155) << 1) | ((x >> 1) & 0x155);
}

// ---------------------------------------------------------------------------
// Radix-4 1024-pt FFT on smem, 256 threads, input base-4-digit-reversed.
// ---------------------------------------------------------------------------
__device__ __forceinline__ void fft1024_r4(float2* s, float sign) {
    #pragma unroll
    for (int st = 0; st < 5; ++st) {
        int Q = 1 << (2 * st);
        int t = threadIdx.x;
        int g = t >> (2 * st);
        int p = t & (Q - 1);
        int base = g * (Q << 2) + p;
        float ang = sign * TWO_PI * (float)p / (float)(Q << 2);
        float s1, c1;
        __sincosf(ang, &s1, &c1);
        float c2 = c1 * c1 - s1 * s1, s2 = 2.0f * c1 * s1;
        float c3 = c1 * c2 - s1 * s2, s3 = c1 * s2 + s1 * c2;
        float2 x0 = s[base];
        float2 x1 = s[base + Q];
        float2 x2 = s[base + 2 * Q];
        float2 x3 = s[base + 3 * Q];
        float2 t1 = make_float2(x1.x * c1 - x1.y * s1, x1.x * s1 + x1.y * c1);
        float2 t2 = make_float2(x2.x * c2 - x2.y * s2, x2.x * s2 + x2.y * c2);
        float2 t3 = make_float2(x3.x * c3 - x3.y * s3, x3.x * s3 + x3.y * c3);
        float2 u0 = make_float2(x0.x + t2.x, x0.y + t2.y);
        float2 u1 = make_float2(x0.x - t2.x, x0.y - t2.y);
        float2 u2 = make_float2(t1.x + t3.x, t1.y + t3.y);
        float2 u3 = make_float2(t1.x - t3.x, t1.y - t3.y);
        float2 v  = make_float2(-u3.y, u3.x);
        s[base]         = make_float2(u0.x + u2.x, u0.y + u2.y);
        s[base + 2 * Q] = make_float2(u0.x - u2.x, u0.y - u2.y);
        s[base + Q]     = make_float2(u1.x + sign * v.x, u1.y + sign * v.y);
        s[base + 3 * Q] = make_float2(u1.x - sign * v.x, u1.y - sign * v.y);
        __syncthreads();
    }
}

// ---------------------------------------------------------------------------
// Kernel 1: apodize + pad + ifftshift + row FFT, two real rows packed/FFT.
// Only columns 0..512 of the output are stored (fft_cols reads only those).
// ---------------------------------------------------------------------------
__global__ void build_fft_rows_kernel(const float* __restrict__ img) {
    __shared__ float2 s[GSZ];
    int b = blockIdx.x;
    float i0a = i0f_dev(ALPHA_C);
    float aA = apod_val(b + 256, i0a);
    float aB = apod_val(b, i0a);
    const float* imA = img + (b + 256) * 512;
    const float* imB = img + b * 512;

    #pragma unroll
    for (int q = 0; q < 4; ++q) {
        int j = threadIdx.x + q * 256;
        float2 z = make_float2(0.0f, 0.0f);
        if (q == 0) {
            int ci = j + 256;
            float ac = apod_val(ci, i0a);
            z.x = imA[ci] * aA * ac;
            z.y = imB[ci] * aB * ac;
        } else if (q == 3) {
            int ci = j - 768;
            float ac = apod_val(ci, i0a);
            z.x = imA[ci] * aA * ac;
            z.y = imB[ci] * aB * ac;
        }
        s[rev4_10(j)] = z;
    }
    __syncthreads();
    fft1024_r4(s, -1.0f);

    float2* baseA = g_grid + (size_t)b * GSZ;
    float2* baseB = g_grid + (size_t)(b + 768) * GSZ;
    for (int k = threadIdx.x; k <= 512; k += 256) {
        float2 Zk = s[k];
        float2 Zn = s[(GSZ - k) & (GSZ - 1)];
        baseA[k] = make_float2(0.5f * (Zk.x + Zn.x), 0.5f * (Zk.y - Zn.y));
        baseB[k] = make_float2(0.5f * (Zk.y + Zn.y), 0.5f * (Zn.x - Zk.x));
    }
}

// ---------------------------------------------------------------------------
// Kernel 2: column FFT — ONLY columns j = 0..512 (Hermitian half-spectrum).
// ---------------------------------------------------------------------------
__global__ void fft_cols_kernel() {
    __shared__ float2 s[GSZ];
    int col = blockIdx.x;            // 0..512
    {
        int t0 = threadIdx.x;
        int t3 = threadIdx.x + 768;
        s[rev4_10(t0)] = g_grid[(size_t)t0 * GSZ + col];
        s[rev4_10(threadIdx.x + 256)] = make_float2(0.0f, 0.0f);
        s[rev4_10(threadIdx.x + 512)] = make_float2(0.0f, 0.0f);
        s[rev4_10(t3)] = g_grid[(size_t)t3 * GSZ + col];
    }
    __syncthreads();
    fft1024_r4(s, -1.0f);
    const float scale = 1.0f / 1024.0f;
    float2* outp = g_specT + (size_t)col * GSZ;
    #pragma unroll
    for (int q = 0; q < 4; ++q) {
        int t = threadIdx.x + q * 256;
        float2 v = s[t];
        outp[t] = make_float2(v.x * scale, v.y * scale);
    }
}

// ---------------------------------------------------------------------------
// Kernel 3: fused gather+IFFT, 128-thread blocks (one angle each, 720 blocks).
// KB weights from a per-block smem LUT (1024 bins, linear interp) — replaces
// 12 x 17-FMA series per point with ~6 ops per weight.
// ---------------------------------------------------------------------------
__global__ void __launch_bounds__(128, 12)
gather_ifft_kernel(const float* __restrict__ ksp, float* __restrict__ out) {
    __shared__ float2 kd[NDET];
    __shared__ float2 sY[3][256];
    __shared__ float wtab[WTN + 2];
    int a = blockIdx.x;
    int lt = threadIdx.x;          // 0..127

    // Build weight LUT: wtab[i] = I0(alpha*sqrt(i/WTN)) / I0(alpha)
    {
        float inv_i0a = 1.0f / i0f_dev(ALPHA_C);
        for (int i = lt; i <= WTN; i += 128) {
            wtab[i] = i0_alpha_sqrt((float)i * (1.0f / (float)WTN)) * inv_i0a;
        }
        if (lt == 0) wtab[WTN + 1] = wtab[WTN];
    }
    __syncthreads();

    const float c = (float)GSZ / TWO_PI;

    for (int d = lt; d < NDHALF; d += 128) {
        int po = a * NDET + d;
        float g1 = fmodf(ksp[po] * c, (float)GSZ);          if (g1 < 0.0f) g1 += (float)GSZ;
        float g2 = fmodf(ksp[KPTS + po] * c, (float)GSZ);   if (g2 < 0.0f) g2 += (float)GSZ;

        int b1 = (int)floorf(g1);
        int b2 = (int)floorf(g2);

        float wx[JW], wy[JW];
        #pragma unroll
        for (int j = 0; j < JW; ++j) {
            float u = g1 - (float)(b1 - 2 + j);
            float xx = fmaxf(fmaf(-u * u, (1.0f / 9.0f), 1.0f), 0.0f) * (float)WTN;
            int i1 = (int)xx;
            float fr = xx - (float)i1;
            float w0t = wtab[i1];
            wx[j] = fmaf(fr, wtab[i1 + 1] - w0t, w0t);

            float v = g2 - (float)(b2 - 2 + j);
            float yy = fmaxf(fmaf(-v * v, (1.0f / 9.0f), 1.0f), 0.0f) * (float)WTN;
            int i2 = (int)yy;
            float fr2 = yy - (float)i2;
            float w1t = wtab[i2];
            wy[j] = fmaf(fr2, wtab[i2 + 1] - w1t, w1t);
        }

        float accx = 0.0f, accy = 0.0f;
        bool xok = (b1 >= 5 && b1 <= 1018);

        if (xok && b2 >= 2 && b2 <= 509) {
            // -------- direct fast path --------
            int s0 = b1 - 2;
            int a0  = s0 & ~1;
            int off = s0 & 1;
            float w0 = off ? 0.0f  : wx[0];
            float w1 = off ? wx[0] : wx[1];
            float w2 = off ? wx[1] : wx[2];
            float w3 = off ? wx[2] : wx[3];
            float w4 = off ? wx[3] : wx[4];
            float w5 = off ? wx[4] : wx[5];
            float w6 = off ? wx[5] : 0.0f;
            const float4* base = (const float4*)(g_specT + ((size_t)(b2 - 2) * GSZ + a0));
            #pragma unroll
            for (int bb = 0; bb < JW; ++bb) {
                const float4* rp = base + (size_t)bb * (GSZ / 2);
                float4 v0 = __ldg(rp);
                float4 v1 = __ldg(rp + 1);
                float4 v2 = __ldg(rp + 2);
                float4 v3 = off ? __ldg(rp + 3) : make_float4(0.f, 0.f, 0.f, 0.f);
                float px = v0.x * w0;
                float py = v0.y * w0;
                px = fmaf(v0.z, w1, px);  py = fmaf(v0.w, w1, py);
                px = fmaf(v1.x, w2, px);  py = fmaf(v1.y, w2, py);
                px = fmaf(v1.z, w3, px);  py = fmaf(v1.w, w3, py);
                px = fmaf(v2.x, w4, px);  py = fmaf(v2.y, w4, py);
                px = fmaf(v2.z, w5, px);  py = fmaf(v2.w, w5, py);
                px = fmaf(v3.x, w6, px);  py = fmaf(v3.y, w6, py);
                accx = fmaf(px, wy[bb], accx);
                accy = fmaf(py, wy[bb], accy);
            }
        } else if (xok && b2 >= 515 && b2 <= 1020) {
            // -------- mirrored fast path (conjugate) --------
            int s0x = 1021 - b1;
            int s0y = 1021 - b2;
            int a0  = s0x & ~1;
            int off = s0x & 1;
            float w0 = off ? 0.0f  : wx[5];
            float w1 = off ? wx[5] : wx[4];
            float w2 = off ? wx[4] : wx[3];
            float w3 = off ? wx[3] : wx[2];
            float w4 = off ? wx[2] : wx[1];
            float w5 = off ? wx[1] : wx[0];
            float w6 = off ? wx[0] : 0.0f;
            const float4* base = (const float4*)(g_specT + ((size_t)s0y * GSZ + a0));
            #pragma unroll
            for (int bb = 0; bb < JW; ++bb) {
                const float4* rp = base + (size_t)bb * (GSZ / 2);
                float4 v0 = __ldg(rp);
                float4 v1 = __ldg(rp + 1);
                float4 v2 = __ldg(rp + 2);
                float4 v3 = off ? __ldg(rp + 3) : make_float4(0.f, 0.f, 0.f, 0.f);
                float px = v0.x * w0;
                float py = v0.y * w0;
                px = fmaf(v0.z, w1, px);  py = fmaf(v0.w, w1, py);
                px = fmaf(v1.x, w2, px);  py = fmaf(v1.y, w2, py);
                px = fmaf(v1.z, w3, px);  py = fmaf(v1.w, w3, py);
                px = fmaf(v2.x, w4, px);  py = fmaf(v2.y, w4, py);
                px = fmaf(v2.z, w5, px);  py = fmaf(v2.w, w5, py);
                px = fmaf(v3.x, w6, px);  py = fmaf(v3.y, w6, py);
                float wyb = wy[5 - bb];
                accx = fmaf(px, wyb, accx);
                accy = fmaf(-py, wyb, accy);
            }
        } else {
            // -------- generic slow path --------
            #pragma unroll
            for (int bb = 0; bb < JW; ++bb) {
                int iyr = (b2 - 2 + bb + GSZ) & (GSZ - 1);
                float px = 0.0f, py = 0.0f;
                if (iyr <= 512) {
                    const float2* rowp = g_specT + (size_t)iyr * GSZ;
                    #pragma unroll
                    for (int aa = 0; aa < JW; ++aa) {
                        int ixr = (b1 - 2 + aa + GSZ) & (GSZ - 1);
                        float2 v = __ldg(&rowp[ixr]);
                        px = fmaf(v.x, wx[aa], px);
                        py = fmaf(v.y, wx[aa], py);
                    }
                } else {
                    const float2* rowp = g_specT + (size_t)(GSZ - iyr) * GSZ;
                    #pragma unroll
                    for (int aa = 0; aa < JW; ++aa) {
                        int ixr = (b1 - 2 + aa + GSZ) & (GSZ - 1);
                        float2 v = __ldg(&rowp[(GSZ - ixr) & (GSZ - 1)]);
                        px = fmaf(v.x, wx[aa], px);
                        py = fmaf(-v.y, wx[aa], py);
                    }
                }
                accx = fmaf(px, wy[bb], accx);
                accy = fmaf(py, wy[bb], accy);
            }
        }

        kd[d] = make_float2(accx, accy);
        if (d > 0 && d < 384) {
            kd[NDET - d] = make_float2(accx, -accy);   // detector-dim Hermitian mirror
        }
    }
    __syncthreads();

    // ---------------- IFFT: 768 = 3 x 256 mixed radix, 128 threads ----------
    #pragma unroll
    for (int r = 0; r < 3; ++r) {
        #pragma unroll
        for (int mq = 0; mq < 2; ++mq) {
            int m = lt + mq * 128;
            int src = (3 * m + r + 384) % NDET;
            sY[r][__brev(m) >> 24] = kd[src];
        }
    }
    __syncthreads();

    #pragma unroll
    for (int st = 0; st < 8; ++st) {
        int half = 1 << st;
        int len = half << 1;
        int grp = lt >> st;
        int pos = lt & (half - 1);
        int ii = grp * len + pos;
        int kk = ii + half;
        float ang = TWO_PI * (float)pos / (float)len;
        float sw, cw;
        __sincosf(ang, &sw, &cw);
        #pragma unroll
        for (int r = 0; r < 3; ++r) {
            float2 b = sY[r][kk];
            float2 wb = make_float2(b.x * cw - b.y * sw, b.x * sw + b.y * cw);
            float2 aa = sY[r][ii];
            sY[r][ii] = make_float2(aa.x + wb.x, aa.y + wb.y);
            sY[r][kk] = make_float2(aa.x - wb.x, aa.y - wb.y);
        }
        __syncthreads();
    }

    // Radix-3 combine with rotation recurrence.
    {
        const float inv = 1.0f / 768.0f;
        float phi = TWO_PI * (float)lt * (1.0f / 768.0f);
        float s1, c1;
        __sincosf(phi, &s1, &c1);
        float c2 = c1 * c1 - s1 * s1;
        float s2 = 2.0f * c1 * s1;
        const float CR = 0.5f,  SR = 0.86602540378f;    // e^{i pi/3}
        const float CQ = -0.5f, SQ = 0.86602540378f;    // e^{i 2pi/3}
        #pragma unroll
        for (int q = 0; q < 6; ++q) {
            int k = lt + q * 128;
            int k0 = k & 255;
            float re = sY[0][k0].x;
            re += sY[1][k0].x * c1 - sY[1][k0].y * s1;
            re += sY[2][k0].x * c2 - sY[2][k0].y * s2;
            out[(size_t)a * NDET + ((k + 384) % NDET)] = re * inv;
            float nc1 = c1 * CR - s1 * SR, ns1 = s1 * CR + c1 * SR;
            c1 = nc1; s1 = ns1;
            float nc2 = c2 * CQ - s2 * SQ, ns2 = s2 * CQ + c2 * SQ;
            c2 = nc2; s2 = ns2;
        }
    }
}

// ---------------------------------------------------------------------------
extern "C" void kernel_launch(void* const* d_in, const int* in_sizes, int n_in,
                              void* d_out, int out_size) {
    const float* img = (const float*)d_in[0];
    const float* ksp = (const float*)d_in[1];
    float* out = (float*)d_out;

    build_fft_rows_kernel<<<256, 256>>>(img);
    fft_cols_kernel<<<513, 256>>>();
    gather_ifft_kernel<<<NANG, 128>>>(ksp, out);
}

// round 14
// speedup vs baseline: 1.2608x; 1.2608x over previous
#include <cuda_runtime.h>
#include <math.h>

#define JW 6
#define ALPHA_C 14.04f            // 2.34 * J
#define GSZ 1024                  // G1 == G2 == 2*H
#define NANG 720
#define NDET 768
#define KPTS (NANG * NDET)
#define NDHALF 385                // detectors gathered: d = 0..384 (Hermitian in detector dim)
#define TWO_PI 6.283185307179586f

__device__ float2 g_grid[GSZ * GSZ];          // row-FFT'd padded image (only cols 0..512 written/read)
__device__ float2 g_specT[513 * GSZ];         // HALF spectrum: rows j=0..512

// ---------------------------------------------------------------------------
// I0 (A&S) — normalizer; cancels against apodization's I0(alpha).
// ---------------------------------------------------------------------------
__device__ __forceinline__ float i0f_dev(float z) {
    if (z < 3.75f) {
        float t = z * (1.0f / 3.75f);
        float t2 = t * t;
        return 1.0f + t2 * (3.5156229f + t2 * (3.0899424f + t2 * (1.2067492f
                     + t2 * (0.2659732f + t2 * (0.0360768f + t2 * 0.0045813f)))));
    } else {
        float ti = 3.75f / z;
        float p = 0.39894228f + ti * (0.01328592f + ti * (0.00225319f
                + ti * (-0.00157565f + ti * (0.00916281f + ti * (-0.02057706f
                + ti * (0.02635537f + ti * (-0.01647633f + ti * 0.00392377f)))))));
        return p * __expf(z) * rsqrtf(z);
    }
}

// I0(alpha*sqrt(x)) on [0,1]: pure-FMA power series in x (k=16).
__device__ __forceinline__ float i0_alpha_sqrt(float x) {
    float s;
    s = 2.764070f;
    s = fmaf(s, x, 14.35870f);
    s = fmaf(s, x, 65.55800f);
    s = fmaf(s, x, 260.7380f);
    s = fmaf(s, x, 894.1610f);
    s = fmaf(s, x, 2612.787f);
    s = fmaf(s, x, 6415.273f);
    s = fmaf(s, x, 13017.90f);
    s = fmaf(s, x, 21396.99f);
    s = fmaf(s, x, 27788.08f);
    s = fmaf(s, x, 27629.97f);
    s = fmaf(s, x, 20184.07f);
    s = fmaf(s, x, 10239.40f);
    s = fmaf(s, x, 3324.453f);
    s = fmaf(s, x, 607.1395f);
    s = fmaf(s, x, 49.28040f);
    s = fmaf(s, x, 1.0f);
    return s;
}

__device__ __forceinline__ float apod_val(int n, float i0a) {
    float u = (float)(n - 256) * (1.0f / (float)GSZ);
    float t = 3.14159265358979f * (float)JW * u;
    float arg = ALPHA_C * ALPHA_C - t * t;
    float s = sqrtf(fabsf(arg) + 1e-20f);
    float sh;
    if (arg > 0.0f) {
        float e = __expf(s);
        sh = 0.5f * (e - 1.0f / e);
    } else {
        sh = __sinf(s);
    }
    float F = (sh / s) * ((float)JW / i0a);
    return 1.0f / F;
}

// Base-4 digit reversal of a 10-bit index (1024 = 4^5).
__device__ __forceinline__ int rev4_10(int t) {
    int x = __brev(t) >> 22;
    return ((x & 0x155) << 1) | ((x >> 1) & 0x155);
}

// ---------------------------------------------------------------------------
// Radix-4 1024-pt FFT on smem, 256 threads, input base-4-digit-reversed.
// ---------------------------------------------------------------------------
__device__ __forceinline__ void fft1024_r4(float2* s, float sign) {
    #pragma unroll
    for (int st = 0; st < 5; ++st) {
        int Q = 1 << (2 * st);
        int t = threadIdx.x;
        int g = t >> (2 * st);
        int p = t & (Q - 1);
        int base = g * (Q << 2) + p;
        float ang = sign * TWO_PI * (float)p / (float)(Q << 2);
        float s1, c1;
        __sincosf(ang, &s1, &c1);
        float c2 = c1 * c1 - s1 * s1, s2 = 2.0f * c1 * s1;
        float c3 = c1 * c2 - s1 * s2, s3 = c1 * s2 + s1 * c2;
        float2 x0 = s[base];
        float2 x1 = s[base + Q];
        float2 x2 = s[base + 2 * Q];
        float2 x3 = s[base + 3 * Q];
        float2 t1 = make_float2(x1.x * c1 - x1.y * s1, x1.x * s1 + x1.y * c1);
        float2 t2 = make_float2(x2.x * c2 - x2.y * s2, x2.x * s2 + x2.y * c2);
        float2 t3 = make_float2(x3.x * c3 - x3.y * s3, x3.x * s3 + x3.y * c3);
        float2 u0 = make_float2(x0.x + t2.x, x0.y + t2.y);
        float2 u1 = make_float2(x0.x - t2.x, x0.y - t2.y);
        float2 u2 = make_float2(t1.x + t3.x, t1.y + t3.y);
        float2 u3 = make_float2(t1.x - t3.x, t1.y - t3.y);
        float2 v  = make_float2(-u3.y, u3.x);
        s[base]         = make_float2(u0.x + u2.x, u0.y + u2.y);
        s[base + 2 * Q] = make_float2(u0.x - u2.x, u0.y - u2.y);
        s[base + Q]     = make_float2(u1.x + sign * v.x, u1.y + sign * v.y);
        s[base + 3 * Q] = make_float2(u1.x - sign * v.x, u1.y - sign * v.y);
        __syncthreads();
    }
}

// ---------------------------------------------------------------------------
// Kernel 1: apodize + pad + ifftshift + row FFT, two real rows packed/FFT.
// Only columns 0..512 of the output are stored (fft_cols reads only those).
// ---------------------------------------------------------------------------
__global__ void build_fft_rows_kernel(const float* __restrict__ img) {
    __shared__ float2 s[GSZ];
    int b = blockIdx.x;
    float i0a = i0f_dev(ALPHA_C);
    float aA = apod_val(b + 256, i0a);
    float aB = apod_val(b, i0a);
    const float* imA = img + (b + 256) * 512;
    const float* imB = img + b * 512;

    #pragma unroll
    for (int q = 0; q < 4; ++q) {
        int j = threadIdx.x + q * 256;
        float2 z = make_float2(0.0f, 0.0f);
        if (q == 0) {
            int ci = j + 256;
            float ac = apod_val(ci, i0a);
            z.x = imA[ci] * aA * ac;
            z.y = imB[ci] * aB * ac;
        } else if (q == 3) {
            int ci = j - 768;
            float ac = apod_val(ci, i0a);
            z.x = imA[ci] * aA * ac;
            z.y = imB[ci] * aB * ac;
        }
        s[rev4_10(j)] = z;
    }
    __syncthreads();
    fft1024_r4(s, -1.0f);

    float2* baseA = g_grid + (size_t)b * GSZ;
    float2* baseB = g_grid + (size_t)(b + 768) * GSZ;
    for (int k = threadIdx.x; k <= 512; k += 256) {
        float2 Zk = s[k];
        float2 Zn = s[(GSZ - k) & (GSZ - 1)];
        baseA[k] = make_float2(0.5f * (Zk.x + Zn.x), 0.5f * (Zk.y - Zn.y));
        baseB[k] = make_float2(0.5f * (Zk.y + Zn.y), 0.5f * (Zn.x - Zk.x));
    }
}

// ---------------------------------------------------------------------------
// Kernel 2: column FFT — ONLY columns j = 0..512 (Hermitian half-spectrum).
// ---------------------------------------------------------------------------
__global__ void fft_cols_kernel() {
    __shared__ float2 s[GSZ];
    int col = blockIdx.x;            // 0..512
    {
        int t0 = threadIdx.x;
        int t3 = threadIdx.x + 768;
        s[rev4_10(t0)] = g_grid[(size_t)t0 * GSZ + col];
        s[rev4_10(threadIdx.x + 256)] = make_float2(0.0f, 0.0f);
        s[rev4_10(threadIdx.x + 512)] = make_float2(0.0f, 0.0f);
        s[rev4_10(t3)] = g_grid[(size_t)t3 * GSZ + col];
    }
    __syncthreads();
    fft1024_r4(s, -1.0f);
    const float scale = 1.0f / 1024.0f;
    float2* outp = g_specT + (size_t)col * GSZ;
    #pragma unroll
    for (int q = 0; q < 4; ++q) {
        int t = threadIdx.x + q * 256;
        float2 v = s[t];
        outp[t] = make_float2(v.x * scale, v.y * scale);
    }
}

// ---------------------------------------------------------------------------
// Gather one nonuniform point (coords pre-normalized to grid units).
// ---------------------------------------------------------------------------
__device__ __forceinline__ float2 gather_point(float g1, float g2) {
    int b1 = (int)floorf(g1);
    int b2 = (int)floorf(g2);

    float wx[JW], wy[JW];
    #pragma unroll
    for (int j = 0; j < JW; ++j) {
        float u = g1 - (float)(b1 - 2 + j);
        float xx = fmaxf(fmaf(-u * u, (1.0f / 9.0f), 1.0f), 0.0f);
        wx[j] = i0_alpha_sqrt(xx);
        float v = g2 - (float)(b2 - 2 + j);
        float yy = fmaxf(fmaf(-v * v, (1.0f / 9.0f), 1.0f), 0.0f);
        wy[j] = i0_alpha_sqrt(yy);
    }

    float accx = 0.0f, accy = 0.0f;
    bool xok = (b1 >= 5 && b1 <= 1018);

    if (xok && b2 >= 2 && b2 <= 509) {
        // -------- direct fast path --------
        int s0 = b1 - 2;
        int a0  = s0 & ~1;
        int off = s0 & 1;
        float w0 = off ? 0.0f  : wx[0];
        float w1 = off ? wx[0] : wx[1];
        float w2 = off ? wx[1] : wx[2];
        float w3 = off ? wx[2] : wx[3];
        float w4 = off ? wx[3] : wx[4];
        float w5 = off ? wx[4] : wx[5];
        float w6 = off ? wx[5] : 0.0f;
        const float4* base = (const float4*)(g_specT + ((size_t)(b2 - 2) * GSZ + a0));
        #pragma unroll
        for (int bb = 0; bb < JW; ++bb) {
            const float4* rp = base + (size_t)bb * (GSZ / 2);
            float4 v0 = __ldg(rp);
            float4 v1 = __ldg(rp + 1);
            float4 v2 = __ldg(rp + 2);
            float4 v3 = off ? __ldg(rp + 3) : make_float4(0.f, 0.f, 0.f, 0.f);
            float px = v0.x * w0;
            float py = v0.y * w0;
            px = fmaf(v0.z, w1, px);  py = fmaf(v0.w, w1, py);
            px = fmaf(v1.x, w2, px);  py = fmaf(v1.y, w2, py);
            px = fmaf(v1.z, w3, px);  py = fmaf(v1.w, w3, py);
            px = fmaf(v2.x, w4, px);  py = fmaf(v2.y, w4, py);
            px = fmaf(v2.z, w5, px);  py = fmaf(v2.w, w5, py);
            px = fmaf(v3.x, w6, px);  py = fmaf(v3.y, w6, py);
            accx = fmaf(px, wy[bb], accx);
            accy = fmaf(py, wy[bb], accy);
        }
    } else if (xok && b2 >= 515 && b2 <= 1020) {
        // -------- mirrored fast path (conjugate) --------
        int s0x = 1021 - b1;
        int s0y = 1021 - b2;
        int a0  = s0x & ~1;
        int off = s0x & 1;
        float w0 = off ? 0.0f  : wx[5];
        float w1 = off ? wx[5] : wx[4];
        float w2 = off ? wx[4] : wx[3];
        float w3 = off ? wx[3] : wx[2];
        float w4 = off ? wx[2] : wx[1];
        float w5 = off ? wx[1] : wx[0];
        float w6 = off ? wx[0] : 0.0f;
        const float4* base = (const float4*)(g_specT + ((size_t)s0y * GSZ + a0));
        #pragma unroll
        for (int bb = 0; bb < JW; ++bb) {
            const float4* rp = base + (size_t)bb * (GSZ / 2);
            float4 v0 = __ldg(rp);
            float4 v1 = __ldg(rp + 1);
            float4 v2 = __ldg(rp + 2);
            float4 v3 = off ? __ldg(rp + 3) : make_float4(0.f, 0.f, 0.f, 0.f);
            float px = v0.x * w0;
            float py = v0.y * w0;
            px = fmaf(v0.z, w1, px);  py = fmaf(v0.w, w1, py);
            px = fmaf(v1.x, w2, px);  py = fmaf(v1.y, w2, py);
            px = fmaf(v1.z, w3, px);  py = fmaf(v1.w, w3, py);
            px = fmaf(v2.x, w4, px);  py = fmaf(v2.y, w4, py);
            px = fmaf(v2.z, w5, px);  py = fmaf(v2.w, w5, py);
            px = fmaf(v3.x, w6, px);  py = fmaf(v3.y, w6, py);
            float wyb = wy[5 - bb];
            accx = fmaf(px, wyb, accx);
            accy = fmaf(-py, wyb, accy);
        }
    } else {
        // -------- generic slow path --------
        #pragma unroll
        for (int bb = 0; bb < JW; ++bb) {
            int iyr = (b2 - 2 + bb + GSZ) & (GSZ - 1);
            float px = 0.0f, py = 0.0f;
            if (iyr <= 512) {
                const float2* rowp = g_specT + (size_t)iyr * GSZ;
                #pragma unroll
                for (int aa = 0; aa < JW; ++aa) {
                    int ixr = (b1 - 2 + aa + GSZ) & (GSZ - 1);
                    float2 v = __ldg(&rowp[ixr]);
                    px = fmaf(v.x, wx[aa], px);
                    py = fmaf(v.y, wx[aa], py);
                }
            } else {
                const float2* rowp = g_specT + (size_t)(GSZ - iyr) * GSZ;
                #pragma unroll
                for (int aa = 0; aa < JW; ++aa) {
                    int ixr = (b1 - 2 + aa + GSZ) & (GSZ - 1);
                    float2 v = __ldg(&rowp[(GSZ - ixr) & (GSZ - 1)]);
                    px = fmaf(v.x, wx[aa], px);
                    py = fmaf(-v.y, wx[aa], py);
                }
            }
            accx = fmaf(px, wy[bb], accx);
            accy = fmaf(py, wy[bb], accy);
        }
    }
    return make_float2(accx, accy);
}

// ---------------------------------------------------------------------------
// Kernel 3: fused gather+IFFT, 128-thread blocks (one angle each, 720 blocks).
// ksp coordinates for all 3 per-thread points prefetched up front so the
// per-iteration front chain (ksp load -> fmod -> weights) overlaps gather
// load latency of the previous iteration.
// ---------------------------------------------------------------------------
__global__ void __launch_bounds__(128, 12)
gather_ifft_kernel(const float* __restrict__ ksp, float* __restrict__ out) {
    __shared__ float2 kd[NDET];
    __shared__ float2 sY[3][256];
    int a = blockIdx.x;
    int lt = threadIdx.x;          // 0..127

    float norm = 1.0f / i0f_dev(ALPHA_C);      // applied once per point pair product
    float norm2 = norm * norm;
    const float c = (float)GSZ / TWO_PI;

    // Prefetch all 3 coordinate pairs (batched independent loads).
    float g1v[3], g2v[3];
    #pragma unroll
    for (int q = 0; q < 3; ++q) {
        int po = a * NDET + lt + q * 128;
        float t1 = fmodf(__ldg(&ksp[po]) * c, (float)GSZ);
        float t2 = fmodf(__ldg(&ksp[KPTS + po]) * c, (float)GSZ);
        g1v[q] = t1 < 0.0f ? t1 + (float)GSZ : t1;
        g2v[q] = t2 < 0.0f ? t2 + (float)GSZ : t2;
    }

    #pragma unroll
    for (int q = 0; q < 3; ++q) {
        int d = lt + q * 128;
        float2 acc = gather_point(g1v[q], g2v[q]);
        acc.x *= norm2;
        acc.y *= norm2;
        kd[d] = acc;
        if (d > 0 && d < 384) {
            kd[NDET - d] = make_float2(acc.x, -acc.y);   // detector-dim Hermitian mirror
        }
    }
    if (lt == 0) {
        int po = a * NDET + 384;
        float t1 = fmodf(__ldg(&ksp[po]) * c, (float)GSZ);
        float t2 = fmodf(__ldg(&ksp[KPTS + po]) * c, (float)GSZ);
        if (t1 < 0.0f) t1 += (float)GSZ;
        if (t2 < 0.0f) t2 += (float)GSZ;
        float2 acc = gather_point(t1, t2);
        kd[384] = make_float2(acc.x * norm2, acc.y * norm2);
    }
    __syncthreads();

    // ---------------- IFFT: 768 = 3 x 256 mixed radix, 128 threads ----------
    #pragma unroll
    for (int r = 0; r < 3; ++r) {
        #pragma unroll
        for (int mq = 0; mq < 2; ++mq) {
            int m = lt + mq * 128;
            int src = (3 * m + r + 384) % NDET;
            sY[r][__brev(m) >> 24] = kd[src];
        }
    }
    __syncthreads();

    #pragma unroll
    for (int st = 0; st < 8; ++st) {
        int half = 1 << st;
        int len = half << 1;
        int grp = lt >> st;
        int pos = lt & (half - 1);
        int ii = grp * len + pos;
        int kk = ii + half;
        float ang = TWO_PI * (float)pos / (float)len;
        float sw, cw;
        __sincosf(ang, &sw, &cw);
        #pragma unroll
        for (int r = 0; r < 3; ++r) {
            float2 b = sY[r][kk];
            float2 wb = make_float2(b.x * cw - b.y * sw, b.x * sw + b.y * cw);
            float2 aa = sY[r][ii];
            sY[r][ii] = make_float2(aa.x + wb.x, aa.y + wb.y);
            sY[r][kk] = make_float2(aa.x - wb.x, aa.y - wb.y);
        }
        __syncthreads();
    }

    // Radix-3 combine with rotation recurrence.
    {
        const float inv = 1.0f / 768.0f;
        float phi = TWO_PI * (float)lt * (1.0f / 768.0f);
        float s1, c1;
        __sincosf(phi, &s1, &c1);
        float c2 = c1 * c1 - s1 * s1;
        float s2 = 2.0f * c1 * s1;
        const float CR = 0.5f,  SR = 0.86602540378f;    // e^{i pi/3}
        const float CQ = -0.5f, SQ = 0.86602540378f;    // e^{i 2pi/3}
        #pragma unroll
        for (int q = 0; q < 6; ++q) {
            int k = lt + q * 128;
            int k0 = k & 255;
            float re = sY[0][k0].x;
            re += sY[1][k0].x * c1 - sY[1][k0].y * s1;
            re += sY[2][k0].x * c2 - sY[2][k0].y * s2;
            out[(size_t)a * NDET + ((k + 384) % NDET)] = re * inv;
            float nc1 = c1 * CR - s1 * SR, ns1 = s1 * CR + c1 * SR;
            c1 = nc1; s1 = ns1;
            float nc2 = c2 * CQ - s2 * SQ, ns2 = s2 * CQ + c2 * SQ;
            c2 = nc2; s2 = ns2;
        }
    }
}

// ---------------------------------------------------------------------------
extern "C" void kernel_launch(void* const* d_in, const int* in_sizes, int n_in,
                              void* d_out, int out_size) {
    const float* img = (const float*)d_in[0];
    const float* ksp = (const float*)d_in[1];
    float* out = (float*)d_out;

    build_fft_rows_kernel<<<256, 256>>>(img);
    fft_cols_kernel<<<513, 256>>>();
    gather_ifft_kernel<<<NANG, 128>>>(ksp, out);
}